// round 3
// baseline (speedup 1.0000x reference)
#include <cuda_runtime.h>

#define TS  50
#define BB  512
#define NE  400
#define NIN 784
#define BE  (BB*NE)
#define BI  (BB*NIN)
#define WSZ (NE*NIN)

// ---------------- persistent device state (no allocs allowed) ----------------
__device__ float g_W[WSZ];
__device__ float g_dw0[WSZ], g_dw1[WSZ];
__device__ float g_scale[NE];
__device__ float g_dg0[BE], g_dg1[BE];
__device__ float g_gine[BE], g_gei[BE], g_gie[BE], g_Iie[BE];
__device__ float g_meme[BE], g_rce[BE], g_memi[BE], g_rci[BE];
__device__ float g_theta[BE], g_tp1[BE], g_tp2[BE];
__device__ float g_a1[BE], g_a2[BE];
__device__ float g_trp[BI];

// ---------------- init ----------------
__global__ void k_init(const float* __restrict__ Wine) {
    int i = blockIdx.x * blockDim.x + threadIdx.x;
    if (i < WSZ) { g_W[i] = Wine[i]; g_dw0[i] = 0.f; g_dw1[i] = 0.f; }
    if (i < BE) {
        g_gine[i] = 0.f; g_gei[i] = 0.f; g_gie[i] = 0.f; g_Iie[i] = 0.f;
        g_meme[i] = -65.f; g_rce[i] = 0.f;
        g_memi[i] = -60.f; g_rci[i] = 0.f;
        g_theta[i] = 20.f; g_tp1[i] = 0.f; g_tp2[i] = 0.f;
    }
    if (i < BI) g_trp[i] = 0.f;
    if (i < NE) g_scale[i] = 1.f;
}

// ---------------- K1: finalize W from previous step's dw partials + row scale ----------------
// W = clip(W*scale_prev + dw0 + dw1, 0, 1);  scale = 78.4 / rowsum(W)
__global__ void __launch_bounds__(256) k_wnorm() {
    int e = blockIdx.x, tid = threadIdx.x;
    float s = g_scale[e];
    int base = e * NIN;
    float sum = 0.f;
    for (int i = tid; i < NIN; i += 256) {
        float w = g_W[base + i] * s + g_dw0[base + i] + g_dw1[base + i];
        w = fminf(fmaxf(w, 0.f), 1.f);
        g_W[base + i] = w;
        sum += w;
    }
    __shared__ float red[8];
    for (int o = 16; o > 0; o >>= 1) sum += __shfl_down_sync(0xffffffffu, sum, o);
    if ((tid & 31) == 0) red[tid >> 5] = sum;
    __syncthreads();
    if (tid == 0) {
        float t = 0.f;
        for (int w = 0; w < 8; w++) t += red[w];
        g_scale[e] = 78.4f / t;
    }
}

// ---------------- K2: dg[b,e] = scale[e] * sum_k x[b,k]*W[e,k]  (split-K=2) ----------------
__global__ void __launch_bounds__(256) k_gemm1(const float* __restrict__ x, int t) {
    const float* xt = x + (size_t)t * BI;
    __shared__ float As[32][65];   // [k][b]
    __shared__ float Bs[32][65];   // [k][e]
    int e0 = blockIdx.x * 64, b0 = blockIdx.y * 64;
    int z = blockIdx.z;
    int kbase = z * 392, kend = kbase + 392;
    int tid = threadIdx.x, tx = tid & 15, ty = tid >> 4;
    float acc[4][4] = {};
    for (int k0 = kbase; k0 < kend; k0 += 32) {
#pragma unroll
        for (int p = 0; p < 8; p++) {
            int l = tid + p * 256;
            int r = l >> 5, c = l & 31;
            int kg = k0 + c;
            As[c][r] = (kg < kend) ? xt[(b0 + r) * NIN + kg] : 0.f;
            int e = e0 + r;
            Bs[c][r] = (kg < kend && e < NE) ? g_W[e * NIN + kg] : 0.f;
        }
        __syncthreads();
#pragma unroll
        for (int k = 0; k < 32; k++) {
            float a[4], bv[4];
#pragma unroll
            for (int j = 0; j < 4; j++) { a[j] = As[k][ty + 16 * j]; bv[j] = Bs[k][tx + 16 * j]; }
#pragma unroll
            for (int jm = 0; jm < 4; jm++)
#pragma unroll
                for (int jn = 0; jn < 4; jn++)
                    acc[jm][jn] += a[jm] * bv[jn];
        }
        __syncthreads();
    }
    float* dg = z ? g_dg1 : g_dg0;
#pragma unroll
    for (int jm = 0; jm < 4; jm++) {
        int b = b0 + ty + jm * 16;
#pragma unroll
        for (int jn = 0; jn < 4; jn++) {
            int e = e0 + tx + jn * 16;
            if (e < NE) dg[b * NE + e] = acc[jm][jn] * g_scale[e];
        }
    }
}

// ---------------- K3: all neuron/synapse/trace dynamics, one block per batch ----------------
__global__ void __launch_bounds__(256) k_neuron(const float* __restrict__ x,
                                                const float* __restrict__ Wei,
                                                const float* __restrict__ Wie,
                                                float* __restrict__ out, int t) {
    int b = blockIdx.x, tid = threadIdx.x;
    const float wie = Wie[1];   // uniform off-diagonal value (17.0)
    float si[2], gie_old[2], meme_new[2];
    __shared__ float red[256];
    float ssum = 0.f;
#pragma unroll
    for (int j = 0; j < 2; j++) {
        int e = tid + j * 256;
        si[j] = 0.f; gie_old[j] = 0.f; meme_new[j] = 0.f;
        if (e < NE) {
            int idx = b * NE + e;
            float dg = g_dg0[idx] + g_dg1[idx];
            float gine = g_gine[idx];
            float meme = g_meme[idx];
            float Iie = g_Iie[idx];
            float Iine = gine * (0.f - meme);           // E_EE = 0
            gine += (dg - gine) * 0.5f;                  // DT/TAU_SYN_E
            g_gine[idx] = gine;
            float theta = g_theta[idx];
            float thr = -52.f - 20.f + theta;
            float rce = g_rce[idx];
            bool act = (rce <= 0.f);
            if (act) meme += (-65.f - meme + (Iine + Iie)) * 0.005f;   // DT/TAU_MEM_E
            rce = fmaxf(rce - 0.5f, 0.f);
            float s = (act && meme > thr) ? 1.f : 0.f;
            if (s > 0.f) { meme = -65.f; rce = 5.f; }
            g_meme[idx] = meme; g_rce[idx] = rce;
            // e -> i (diagonal W_ei)
            float dgei = s * Wei[e * NE + e];
            float gei = g_gei[idx];
            float memi = g_memi[idx];
            float Iei = gei * (0.f - memi);              // E_EI = 0
            gei += (dgei - gei) * 0.5f;
            g_gei[idx] = gei;
            float rci = g_rci[idx];
            bool acti = (rci <= 0.f);
            if (acti) memi += (-60.f - memi + Iei) * 0.05f;            // DT/TAU_MEM_I
            rci = fmaxf(rci - 0.5f, 0.f);
            float s_i = (acti && memi > -40.f) ? 1.f : 0.f;
            if (s_i > 0.f) { memi = -45.f; rci = 2.f; }
            g_memi[idx] = memi; g_rci[idx] = rci;
            // homeostasis + traces + STDP operands
            theta = theta * (1.0f - 0.5f / 1e7f) + 0.05f * s;
            g_theta[idx] = theta;
            float tp1 = g_tp1[idx], tp2 = g_tp2[idx];
            float r1 = tp1 * (1.0f - 0.5f / 20.0f);
            float r2 = tp2 * (1.0f - 0.5f / 40.0f);
            bool fired = (s > 0.9f);
            g_tp1[idx] = fired ? 1.f : r1;
            g_tp2[idx] = fired ? 1.f : r2;
            g_a1[idx] = 1e-4f * r1;                      // NU_PRE folded
            g_a2[idx] = fired ? 0.01f * r2 : 0.f;        // NU_POST * spike * ret2
            out[(size_t)t * BE + idx] = s;
            si[j] = s_i; gie_old[j] = g_gie[idx]; meme_new[j] = meme;
        }
        ssum += si[j];
    }
    red[tid] = ssum;
    __syncthreads();
    for (int o = 128; o > 0; o >>= 1) {
        if (tid < o) red[tid] += red[tid + o];
        __syncthreads();
    }
    float S = red[0];
#pragma unroll
    for (int j = 0; j < 2; j++) {
        int e = tid + j * 256;
        if (e < NE) {
            int idx = b * NE + e;
            float dgie = wie * (S - si[j]);              // (ones-eye)*c structure, exact
            float gie = gie_old[j];
            g_Iie[idx] = gie * (-100.f - meme_new[j]);   // uses NEW mem_e, OLD g_ie
            g_gie[idx] = gie + (dgie - gie) * 0.25f;     // DT/TAU_SYN_I
        }
    }
    // trace_pre update for this batch row
    const float* xt = x + (size_t)t * BI + (size_t)b * NIN;
    float* trp = g_trp + (size_t)b * NIN;
    for (int i = tid; i < NIN; i += 256) {
        float xv = xt[i];
        float tv;
        if (t == 0) tv = xv;
        else tv = (xv > 0.9f) ? 1.f : trp[i] * (1.0f - 0.5f / 20.0f);
        trp[i] = tv;
    }
}

// ---------------- K4: STDP dual GEMM, dw[e,i] = sum_b a1[b,e]*x[b,i] + a2[b,e]*trp[b,i] ----------------
__global__ void __launch_bounds__(256) k_stdp(const float* __restrict__ x, int t) {
    const float* xt = x + (size_t)t * BI;
    __shared__ float A1s[16][65], A2s[16][65], Xs[16][65], Ts[16][65];
    int i0 = blockIdx.x * 64, e0 = blockIdx.y * 64;
    int z = blockIdx.z;
    int kbase = z * 256;
    int tid = threadIdx.x, tx = tid & 15, ty = tid >> 4;
    float acc[4][4] = {};
    for (int k0 = 0; k0 < 256; k0 += 16) {
        int kk = kbase + k0;
#pragma unroll
        for (int p = 0; p < 4; p++) {
            int l = tid + p * 256;
            int r = l >> 6, c = l & 63;
            int kb = kk + r;
            int e = e0 + c;
            A1s[r][c] = (e < NE) ? g_a1[kb * NE + e] : 0.f;
            A2s[r][c] = (e < NE) ? g_a2[kb * NE + e] : 0.f;
            int ii = i0 + c;
            Xs[r][c] = (ii < NIN) ? xt[kb * NIN + ii] : 0.f;
            Ts[r][c] = (ii < NIN) ? g_trp[kb * NIN + ii] : 0.f;
        }
        __syncthreads();
#pragma unroll
        for (int k = 0; k < 16; k++) {
            float a1v[4], a2v[4], xv[4], tv[4];
#pragma unroll
            for (int j = 0; j < 4; j++) {
                a1v[j] = A1s[k][ty + 16 * j];
                a2v[j] = A2s[k][ty + 16 * j];
                xv[j]  = Xs[k][tx + 16 * j];
                tv[j]  = Ts[k][tx + 16 * j];
            }
#pragma unroll
            for (int jm = 0; jm < 4; jm++)
#pragma unroll
                for (int jn = 0; jn < 4; jn++)
                    acc[jm][jn] += a1v[jm] * xv[jn] + a2v[jm] * tv[jn];
        }
        __syncthreads();
    }
    float* dw = z ? g_dw1 : g_dw0;
#pragma unroll
    for (int jm = 0; jm < 4; jm++) {
        int e = e0 + ty + 16 * jm;
        if (e < NE) {
#pragma unroll
            for (int jn = 0; jn < 4; jn++) {
                int ii = i0 + tx + 16 * jn;
                if (ii < NIN) dw[e * NIN + ii] = acc[jm][jn];
            }
        }
    }
}

// ---------------- launch ----------------
extern "C" void kernel_launch(void* const* d_in, const int* in_sizes, int n_in,
                              void* d_out, int out_size) {
    // identify inputs by size for robustness: x=20070400, W_ine=313600, W_ei/W_ie=160000 (order)
    const float* x = nullptr; const float* Wine = nullptr;
    const float* Wei = nullptr; const float* Wie = nullptr;
    for (int i = 0; i < n_in; i++) {
        int sz = in_sizes[i];
        if (sz == TS * BI) x = (const float*)d_in[i];
        else if (sz == WSZ) Wine = (const float*)d_in[i];
        else if (sz == NE * NE) { if (!Wei) Wei = (const float*)d_in[i]; else Wie = (const float*)d_in[i]; }
    }
    float* out = (float*)d_out;

    k_init<<<(BI + 255) / 256, 256>>>(Wine);
    for (int t = 0; t < TS; t++) {
        k_wnorm<<<NE, 256>>>();
        k_gemm1<<<dim3(7, 8, 2), 256>>>(x, t);
        k_neuron<<<BB, 256>>>(x, Wei, Wie, out, t);
        k_stdp<<<dim3(13, 7, 2), 256>>>(x, t);
    }
}

// round 4
// speedup vs baseline: 1.9451x; 1.9451x over previous
#include <cuda_runtime.h>

#define TS  50
#define BB  512
#define NE  400
#define NIN 784
#define BE  (BB*NE)
#define BI  (BB*NIN)
#define WSZ (NE*NIN)

typedef unsigned long long u64;

// ---------------- f32x2 helpers ----------------
__device__ __forceinline__ u64 fma2(u64 a, u64 b, u64 c) {
    u64 d;
    asm("fma.rn.f32x2 %0, %1, %2, %3;" : "=l"(d) : "l"(a), "l"(b), "l"(c));
    return d;
}
__device__ __forceinline__ u64 pk2(float lo, float hi) {
    u64 r; asm("mov.b64 %0, {%1, %2};" : "=l"(r) : "f"(lo), "f"(hi)); return r;
}
__device__ __forceinline__ float2 upk2(u64 v) {
    float2 u; asm("mov.b64 {%0, %1}, %2;" : "=f"(u.x), "=f"(u.y) : "l"(v)); return u;
}

// ---------------- persistent device state ----------------
__device__ float g_W[WSZ];
__device__ float g_dw0[WSZ], g_dw1[WSZ];
__device__ float g_scale[NE];
__device__ float g_dg0[BE], g_dg1[BE], g_dg2[BE], g_dg3[BE];
__device__ float g_gine[BE], g_gei[BE], g_gie[BE], g_Iie[BE];
__device__ float g_meme[BE], g_rce[BE], g_memi[BE], g_rci[BE];
__device__ float g_theta[BE], g_tp1[BE], g_tp2[BE];
__device__ float g_a1[BE], g_a2[BE];
__device__ float g_trp[BI];

// ---------------- init ----------------
__global__ void k_init(const float* __restrict__ Wine) {
    int i = blockIdx.x * blockDim.x + threadIdx.x;
    if (i < WSZ) { g_W[i] = Wine[i]; g_dw0[i] = 0.f; g_dw1[i] = 0.f; }
    if (i < BE) {
        g_gine[i] = 0.f; g_gei[i] = 0.f; g_gie[i] = 0.f; g_Iie[i] = 0.f;
        g_meme[i] = -65.f; g_rce[i] = 0.f;
        g_memi[i] = -60.f; g_rci[i] = 0.f;
        g_theta[i] = 20.f; g_tp1[i] = 0.f; g_tp2[i] = 0.f;
    }
    if (i < BI) g_trp[i] = 0.f;
    if (i < NE) g_scale[i] = 1.f;
}

// ---------------- K1: W = clip(W*scale_prev + dw0 + dw1); scale = 78.4/rowsum ----------------
__global__ void __launch_bounds__(256) k_wnorm() {
    int e = blockIdx.x, tid = threadIdx.x;
    float s = g_scale[e];
    int base = e * NIN;
    float sum = 0.f;
    for (int i = tid; i < NIN; i += 256) {
        float w = g_W[base + i] * s + g_dw0[base + i] + g_dw1[base + i];
        w = fminf(fmaxf(w, 0.f), 1.f);
        g_W[base + i] = w;
        sum += w;
    }
    __shared__ float red[8];
    for (int o = 16; o > 0; o >>= 1) sum += __shfl_down_sync(0xffffffffu, sum, o);
    if ((tid & 31) == 0) red[tid >> 5] = sum;
    __syncthreads();
    if (tid == 0) {
        float t = 0.f;
        for (int w = 0; w < 8; w++) t += red[w];
        g_scale[e] = 78.4f / t;
    }
}

// ---------------- K2: dg[b,e] = scale[e] * sum_k x[b,k]*W[e,k]  (split-K=4, f32x2 k-packed) ----------------
// Tile 64b x 64e, BK=28 (196 = 7*28 per split). Shared rows [row][k], stride 36 (16B-aligned, conflict-free).
__global__ void __launch_bounds__(256) k_gemm1(const float* __restrict__ x, int t) {
    const float* xt = x + (size_t)t * BI;
    __shared__ __align__(16) float As[64 * 36];
    __shared__ __align__(16) float Bs[64 * 36];
    int e0 = blockIdx.x * 64, b0 = blockIdx.y * 64;
    int z = blockIdx.z;
    int kz = z * 196;
    int tid = threadIdx.x, tx = tid & 15, ty = tid >> 4;
    u64 acc[4][4];
#pragma unroll
    for (int jm = 0; jm < 4; jm++)
#pragma unroll
        for (int jn = 0; jn < 4; jn++) acc[jm][jn] = 0ULL;

    for (int kt = 0; kt < 7; kt++) {
        int kbase = kz + kt * 28;
#pragma unroll
        for (int p = 0; p < 2; p++) {
            int c = tid + p * 256;
            if (c < 448) {
                int row = c / 7, kc = c % 7;
                int kg = kbase + kc * 4;
                float4 v = *(const float4*)&xt[(b0 + row) * NIN + kg];
                *(float4*)&As[row * 36 + kc * 4] = v;
                int e = e0 + row;
                float4 w = (e < NE) ? *(const float4*)&g_W[e * NIN + kg]
                                    : make_float4(0.f, 0.f, 0.f, 0.f);
                *(float4*)&Bs[row * 36 + kc * 4] = w;
            }
        }
        __syncthreads();
#pragma unroll
        for (int kk = 0; kk < 28; kk += 4) {
            float4 av[4], bv[4];
#pragma unroll
            for (int jm = 0; jm < 4; jm++) av[jm] = *(const float4*)&As[(ty + 16 * jm) * 36 + kk];
#pragma unroll
            for (int jn = 0; jn < 4; jn++) bv[jn] = *(const float4*)&Bs[(tx + 16 * jn) * 36 + kk];
#pragma unroll
            for (int jm = 0; jm < 4; jm++) {
                u64 a0 = pk2(av[jm].x, av[jm].y);
                u64 a1 = pk2(av[jm].z, av[jm].w);
#pragma unroll
                for (int jn = 0; jn < 4; jn++) {
                    acc[jm][jn] = fma2(a0, pk2(bv[jn].x, bv[jn].y), acc[jm][jn]);
                    acc[jm][jn] = fma2(a1, pk2(bv[jn].z, bv[jn].w), acc[jm][jn]);
                }
            }
        }
        __syncthreads();
    }
    float* dg = (z == 0) ? g_dg0 : (z == 1) ? g_dg1 : (z == 2) ? g_dg2 : g_dg3;
#pragma unroll
    for (int jn = 0; jn < 4; jn++) {
        int e = e0 + tx + 16 * jn;
        if (e < NE) {
            float scl = g_scale[e];
#pragma unroll
            for (int jm = 0; jm < 4; jm++) {
                float2 u = upk2(acc[jm][jn]);
                dg[(b0 + ty + 16 * jm) * NE + e] = (u.x + u.y) * scl;
            }
        }
    }
}

// ---------------- K3: neuron/synapse/trace dynamics, one block per batch (512 thr) ----------------
__global__ void __launch_bounds__(512) k_neuron(const float* __restrict__ x,
                                                const float* __restrict__ Wei,
                                                const float* __restrict__ Wie,
                                                float* __restrict__ out, int t) {
    int b = blockIdx.x, tid = threadIdx.x;
    const float wie = Wie[1];   // uniform off-diagonal (17.0)
    __shared__ float red[16];
    __shared__ float Sb;
    float s_i = 0.f, gie_old = 0.f, meme_new = 0.f;
    bool active = tid < NE;
    int idx = b * NE + tid;
    if (active) {
        float dg = g_dg0[idx] + g_dg1[idx] + g_dg2[idx] + g_dg3[idx];
        float gine = g_gine[idx];
        float meme = g_meme[idx];
        float Iie = g_Iie[idx];
        float Iine = gine * (0.f - meme);                 // E_EE = 0
        gine += (dg - gine) * 0.5f;                        // DT/TAU_SYN_E
        g_gine[idx] = gine;
        float theta = g_theta[idx];
        float thr = -52.f - 20.f + theta;
        float rce = g_rce[idx];
        bool act = (rce <= 0.f);
        if (act) meme += (-65.f - meme + (Iine + Iie)) * 0.005f;   // DT/TAU_MEM_E
        rce = fmaxf(rce - 0.5f, 0.f);
        float s = (act && meme > thr) ? 1.f : 0.f;
        if (s > 0.f) { meme = -65.f; rce = 5.f; }
        g_meme[idx] = meme; g_rce[idx] = rce;
        // e -> i (diagonal W_ei)
        float dgei = s * Wei[tid * NE + tid];
        float gei = g_gei[idx];
        float memi = g_memi[idx];
        float Iei = gei * (0.f - memi);                   // E_EI = 0
        gei += (dgei - gei) * 0.5f;
        g_gei[idx] = gei;
        float rci = g_rci[idx];
        bool acti = (rci <= 0.f);
        if (acti) memi += (-60.f - memi + Iei) * 0.05f;   // DT/TAU_MEM_I
        rci = fmaxf(rci - 0.5f, 0.f);
        s_i = (acti && memi > -40.f) ? 1.f : 0.f;
        if (s_i > 0.f) { memi = -45.f; rci = 2.f; }
        g_memi[idx] = memi; g_rci[idx] = rci;
        // homeostasis + traces + STDP operands
        theta = theta * (1.0f - 0.5f / 1e7f) + 0.05f * s;
        g_theta[idx] = theta;
        float tp1 = g_tp1[idx], tp2 = g_tp2[idx];
        float r1 = tp1 * (1.0f - 0.5f / 20.0f);
        float r2 = tp2 * (1.0f - 0.5f / 40.0f);
        bool fired = (s > 0.9f);
        g_tp1[idx] = fired ? 1.f : r1;
        g_tp2[idx] = fired ? 1.f : r2;
        g_a1[idx] = 1e-4f * r1;                           // NU_PRE folded
        g_a2[idx] = fired ? 0.01f * r2 : 0.f;             // NU_POST * spike * ret2
        out[(size_t)t * BE + idx] = s;
        gie_old = g_gie[idx]; meme_new = meme;
    }
    // block-sum of spike_i (exact: 0/1 floats)
    float v = s_i;
#pragma unroll
    for (int o = 16; o > 0; o >>= 1) v += __shfl_down_sync(0xffffffffu, v, o);
    if ((tid & 31) == 0) red[tid >> 5] = v;
    __syncthreads();
    if (tid == 0) {
        float S = 0.f;
        for (int w = 0; w < 16; w++) S += red[w];
        Sb = S;
    }
    __syncthreads();
    float S = Sb;
    if (active) {
        float dgie = wie * (S - s_i);                      // (ones-eye)*c, exact
        g_Iie[idx] = gie_old * (-100.f - meme_new);        // NEW mem_e, OLD g_ie
        g_gie[idx] = gie_old + (dgie - gie_old) * 0.25f;   // DT/TAU_SYN_I
    }
    // trace_pre update for this batch row
    const float* xt = x + (size_t)t * BI + (size_t)b * NIN;
    float* trp = g_trp + (size_t)b * NIN;
    for (int i = tid; i < NIN; i += 512) {
        float xv = xt[i];
        float tv;
        if (t == 0) tv = xv;
        else tv = (xv > 0.9f) ? 1.f : trp[i] * (1.0f - 0.5f / 20.0f);
        trp[i] = tv;
    }
}

// ---------------- K4: STDP dual GEMM (split-K=2, f32x2 output-packed over i) ----------------
// dw[e,i] = sum_b a1[b,e]*x[b,i] + a2[b,e]*trp[b,i].  Tile 64e x 64i, BK=16.
__global__ void __launch_bounds__(256) k_stdp(const float* __restrict__ x, int t) {
    const float* xt = x + (size_t)t * BI;
    __shared__ __align__(16) float A1s[16 * 68];
    __shared__ __align__(16) float A2s[16 * 68];
    __shared__ __align__(16) float Xs[16 * 68];
    __shared__ __align__(16) float Ts[16 * 68];
    int i0 = blockIdx.x * 64, e0 = blockIdx.y * 64;
    int z = blockIdx.z;
    int bz = z * 256;
    int tid = threadIdx.x, tx = tid & 15, ty = tid >> 4;
    u64 acc[4][2];
#pragma unroll
    for (int jm = 0; jm < 4; jm++) { acc[jm][0] = 0ULL; acc[jm][1] = 0ULL; }

    int lrow = tid >> 4;           // 0..15  (k row)
    int lcol = (tid & 15) * 4;     // 0..60  (column chunk)
    bool e_ok = (e0 + lcol + 3) < NE;
    bool i_ok = (i0 + lcol + 3) < NIN;
    const float4 z4 = make_float4(0.f, 0.f, 0.f, 0.f);

    for (int kt = 0; kt < 16; kt++) {
        int kb = bz + kt * 16 + lrow;
        *(float4*)&A1s[lrow * 68 + lcol] = e_ok ? *(const float4*)&g_a1[kb * NE + e0 + lcol] : z4;
        *(float4*)&A2s[lrow * 68 + lcol] = e_ok ? *(const float4*)&g_a2[kb * NE + e0 + lcol] : z4;
        *(float4*)&Xs[lrow * 68 + lcol]  = i_ok ? *(const float4*)&xt[kb * NIN + i0 + lcol] : z4;
        *(float4*)&Ts[lrow * 68 + lcol]  = i_ok ? *(const float4*)&g_trp[kb * NIN + i0 + lcol] : z4;
        __syncthreads();
#pragma unroll
        for (int k = 0; k < 16; k++) {
            float4 a1v = *(const float4*)&A1s[k * 68 + ty * 4];
            float4 a2v = *(const float4*)&A2s[k * 68 + ty * 4];
            float4 xv  = *(const float4*)&Xs[k * 68 + tx * 4];
            float4 tv  = *(const float4*)&Ts[k * 68 + tx * 4];
            u64 xp0 = pk2(xv.x, xv.y), xp1 = pk2(xv.z, xv.w);
            u64 tp0 = pk2(tv.x, tv.y), tp1 = pk2(tv.z, tv.w);
            float a1a[4] = {a1v.x, a1v.y, a1v.z, a1v.w};
            float a2a[4] = {a2v.x, a2v.y, a2v.z, a2v.w};
#pragma unroll
            for (int jm = 0; jm < 4; jm++) {
                u64 a1b = pk2(a1a[jm], a1a[jm]);
                u64 a2b = pk2(a2a[jm], a2a[jm]);
                acc[jm][0] = fma2(a1b, xp0, acc[jm][0]);
                acc[jm][0] = fma2(a2b, tp0, acc[jm][0]);
                acc[jm][1] = fma2(a1b, xp1, acc[jm][1]);
                acc[jm][1] = fma2(a2b, tp1, acc[jm][1]);
            }
        }
        __syncthreads();
    }
    float* dw = z ? g_dw1 : g_dw0;
    int ii = i0 + tx * 4;
    if (ii + 3 < NIN) {
#pragma unroll
        for (int jm = 0; jm < 4; jm++) {
            int e = e0 + ty * 4 + jm;
            if (e < NE) {
                float2 u0 = upk2(acc[jm][0]);
                float2 u1 = upk2(acc[jm][1]);
                float4 o = make_float4(u0.x, u0.y, u1.x, u1.y);
                *(float4*)&dw[e * NIN + ii] = o;
            }
        }
    }
}

// ---------------- launch ----------------
extern "C" void kernel_launch(void* const* d_in, const int* in_sizes, int n_in,
                              void* d_out, int out_size) {
    const float* x = nullptr; const float* Wine = nullptr;
    const float* Wei = nullptr; const float* Wie = nullptr;
    for (int i = 0; i < n_in; i++) {
        int sz = in_sizes[i];
        if (sz == TS * BI) x = (const float*)d_in[i];
        else if (sz == WSZ) Wine = (const float*)d_in[i];
        else if (sz == NE * NE) { if (!Wei) Wei = (const float*)d_in[i]; else Wie = (const float*)d_in[i]; }
    }
    float* out = (float*)d_out;

    k_init<<<(BI + 255) / 256, 256>>>(Wine);
    for (int t = 0; t < TS; t++) {
        k_wnorm<<<NE, 256>>>();
        k_gemm1<<<dim3(7, 8, 4), 256>>>(x, t);
        k_neuron<<<BB, 512>>>(x, Wei, Wie, out, t);
        k_stdp<<<dim3(13, 7, 2), 256>>>(x, t);
    }
}

// round 7
// speedup vs baseline: 2.0373x; 1.0474x over previous
#include <cuda_runtime.h>

#define TS  50
#define BB  512
#define NE  400
#define NIN 784
#define BE  (BB*NE)
#define BI  (BB*NIN)
#define WSZ (NE*NIN)
#define NBLK 296
#define GZ  5     // gemm1 split-K parts (K=784 -> 160,160,160,160,144)
#define SZ  3     // stdp  split-K parts (B=512 -> 176,176,160)

typedef unsigned long long u64;

// ---------------- f32x2 helpers ----------------
__device__ __forceinline__ u64 fma2(u64 a, u64 b, u64 c) {
    u64 d;
    asm("fma.rn.f32x2 %0, %1, %2, %3;" : "=l"(d) : "l"(a), "l"(b), "l"(c));
    return d;
}
__device__ __forceinline__ u64 pk2(float lo, float hi) {
    u64 r; asm("mov.b64 %0, {%1, %2};" : "=l"(r) : "f"(lo), "f"(hi)); return r;
}
__device__ __forceinline__ float2 upk2(u64 v) {
    float2 u; asm("mov.b64 {%0, %1}, %2;" : "=f"(u.x), "=f"(u.y) : "l"(v)); return u;
}

// ---------------- persistent device state ----------------
__device__ float g_W[WSZ];
__device__ float g_dw[SZ * WSZ];
__device__ float g_scale[NE];
__device__ float g_dg[GZ * BE];
__device__ float g_gine[BE], g_gei[BE], g_gie[BE], g_Iie[BE];
__device__ float g_meme[BE], g_rce[BE], g_memi[BE], g_rci[BE];
__device__ float g_theta[BE], g_tp1[BE], g_tp2[BE];
__device__ float g_a1[BE], g_a2[BE];
__device__ float g_trp[BI];

// ---------------- grid barrier ----------------
__device__ unsigned g_count;
__device__ unsigned g_gen;

__device__ __forceinline__ void gbar() {
    __threadfence();               // publish this thread's writes (L2)
    __syncthreads();
    if (threadIdx.x == 0) {
        unsigned gen = *(volatile unsigned*)&g_gen;
        if (atomicAdd(&g_count, 1u) == NBLK - 1) {
            g_count = 0;
            __threadfence();
            *(volatile unsigned*)&g_gen = gen + 1;
        } else {
            while (*(volatile unsigned*)&g_gen == gen) { __nanosleep(40); }
        }
        __threadfence();           // gpu-scope fence: CCTL.IVALL -> drop stale L1
    }
    __syncthreads();
}

// ---------------- neuron state update (one excitatory/inhibitory pair) ----------------
__device__ __forceinline__ void neuron_update(int idx, float wei_diag,
                                              float* __restrict__ out, size_t out_off,
                                              float& s_i_out, float& gie_old_out, float& meme_out) {
    float dg = 0.f;
#pragma unroll
    for (int z = 0; z < GZ; z++) dg += g_dg[z * BE + idx];
    float gine = g_gine[idx];
    float meme = g_meme[idx];
    float Iie = g_Iie[idx];
    float Iine = gine * (0.f - meme);                 // E_EE = 0
    gine += (dg - gine) * 0.5f;                        // DT/TAU_SYN_E
    g_gine[idx] = gine;
    float theta = g_theta[idx];
    float thr = -52.f - 20.f + theta;
    float rce = g_rce[idx];
    bool act = (rce <= 0.f);
    if (act) meme += (-65.f - meme + (Iine + Iie)) * 0.005f;   // DT/TAU_MEM_E
    rce = fmaxf(rce - 0.5f, 0.f);
    float s = (act && meme > thr) ? 1.f : 0.f;
    if (s > 0.f) { meme = -65.f; rce = 5.f; }
    g_meme[idx] = meme; g_rce[idx] = rce;
    // e -> i (diagonal W_ei)
    float dgei = s * wei_diag;
    float gei = g_gei[idx];
    float memi = g_memi[idx];
    float Iei = gei * (0.f - memi);                   // E_EI = 0
    gei += (dgei - gei) * 0.5f;
    g_gei[idx] = gei;
    float rci = g_rci[idx];
    bool acti = (rci <= 0.f);
    if (acti) memi += (-60.f - memi + Iei) * 0.05f;   // DT/TAU_MEM_I
    rci = fmaxf(rci - 0.5f, 0.f);
    float s_i = (acti && memi > -40.f) ? 1.f : 0.f;
    if (s_i > 0.f) { memi = -45.f; rci = 2.f; }
    g_memi[idx] = memi; g_rci[idx] = rci;
    // homeostasis + traces + STDP operands
    theta = theta * (1.0f - 0.5f / 1e7f) + 0.05f * s;
    g_theta[idx] = theta;
    float tp1 = g_tp1[idx], tp2 = g_tp2[idx];
    float r1 = tp1 * (1.0f - 0.5f / 20.0f);
    float r2 = tp2 * (1.0f - 0.5f / 40.0f);
    bool fired = (s > 0.9f);
    g_tp1[idx] = fired ? 1.f : r1;
    g_tp2[idx] = fired ? 1.f : r2;
    g_a1[idx] = 1e-4f * r1;                           // NU_PRE folded
    g_a2[idx] = fired ? 0.01f * r2 : 0.f;             // NU_POST * spike * ret2
    out[out_off + idx] = s;
    s_i_out = s_i; gie_old_out = g_gie[idx]; meme_out = meme;
}

// ---------------- the single persistent kernel ----------------
__global__ void __launch_bounds__(256, 2) k_persist(const float* __restrict__ x,
                                                    const float* __restrict__ Wei,
                                                    const float* __restrict__ Wie,
                                                    const float* __restrict__ Wine,
                                                    float* __restrict__ out) {
    __shared__ __align__(16) float smbuf[4608];     // 18.4KB: unioned per phase
    const int bid = blockIdx.x, tid = threadIdx.x;
    const int gtid = bid * 256 + tid;
    const float4 f4z = make_float4(0.f, 0.f, 0.f, 0.f);

    // ---- Phase I: init all state (covers max extent SZ*WSZ = 940800) ----
    for (int i = gtid; i < SZ * WSZ; i += NBLK * 256) {
        if (i < WSZ) g_W[i] = Wine[i];
        g_dw[i] = 0.f;
        if (i < BE) {
            g_gine[i] = 0.f; g_gei[i] = 0.f; g_gie[i] = 0.f; g_Iie[i] = 0.f;
            g_meme[i] = -65.f; g_rce[i] = 0.f;
            g_memi[i] = -60.f; g_rci[i] = 0.f;
            g_theta[i] = 20.f; g_tp1[i] = 0.f; g_tp2[i] = 0.f;
        }
        if (i < BI) g_trp[i] = 0.f;
        if (i < NE) g_scale[i] = 1.f;
    }
    gbar();

    const float wie = Wie[1];    // uniform off-diagonal (17.0)

    for (int t = 0; t < TS; t++) {
        const float* xt = x + (size_t)t * BI;

        // ---- Phase W: W = clip(W*scale_prev + sum(dw)); scale = 78.4/rowsum ----
        for (int e = bid; e < NE; e += NBLK) {
            float s = g_scale[e];
            int base = e * NIN;
            float sum = 0.f;
            for (int i = tid; i < NIN; i += 256) {
                float w = g_W[base + i] * s;
#pragma unroll
                for (int z = 0; z < SZ; z++) w += g_dw[z * WSZ + base + i];
                w = fminf(fmaxf(w, 0.f), 1.f);
                g_W[base + i] = w;
                sum += w;
            }
            for (int o = 16; o > 0; o >>= 1) sum += __shfl_down_sync(0xffffffffu, sum, o);
            if ((tid & 31) == 0) smbuf[tid >> 5] = sum;
            __syncthreads();
            if (tid == 0) {
                float tt = 0.f;
                for (int w = 0; w < 8; w++) tt += smbuf[w];
                g_scale[e] = 78.4f / tt;
            }
            __syncthreads();
        }
        gbar();

        // ---- Phase G: dg_z[b,e] = scale[e] * sum_{k in z} x[b,k]*W[e,k] ----
        if (bid < 7 * 8 * GZ) {
            int z = bid / 56, r = bid % 56;
            int ex = r % 7, by = r / 7;
            int e0 = ex * 64, b0 = by * 64;
            int kz = z * 160;
            int nk = (z == GZ - 1) ? 9 : 10;            // chunks of BK=16
            float* As = smbuf;                          // [64][20]
            float* Bs = smbuf + 1280;                   // [64][20]
            int tx = tid & 15, ty = tid >> 4;
            int lrow = tid >> 2, lk = (tid & 3) * 4;
            u64 acc[4][4];
#pragma unroll
            for (int jm = 0; jm < 4; jm++)
#pragma unroll
                for (int jn = 0; jn < 4; jn++) acc[jm][jn] = 0ULL;

            for (int c = 0; c < nk; c++) {
                int kg = kz + c * 16 + lk;
                *(float4*)&As[lrow * 20 + lk] = *(const float4*)&xt[(b0 + lrow) * NIN + kg];
                int e = e0 + lrow;
                *(float4*)&Bs[lrow * 20 + lk] = (e < NE) ? *(const float4*)&g_W[e * NIN + kg] : f4z;
                __syncthreads();
#pragma unroll
                for (int kk = 0; kk < 16; kk += 4) {
                    float4 av[4], bv[4];
#pragma unroll
                    for (int jm = 0; jm < 4; jm++) av[jm] = *(const float4*)&As[(ty + 16 * jm) * 20 + kk];
#pragma unroll
                    for (int jn = 0; jn < 4; jn++) bv[jn] = *(const float4*)&Bs[(tx + 16 * jn) * 20 + kk];
#pragma unroll
                    for (int jm = 0; jm < 4; jm++) {
                        u64 a0 = pk2(av[jm].x, av[jm].y);
                        u64 a1 = pk2(av[jm].z, av[jm].w);
#pragma unroll
                        for (int jn = 0; jn < 4; jn++) {
                            acc[jm][jn] = fma2(a0, pk2(bv[jn].x, bv[jn].y), acc[jm][jn]);
                            acc[jm][jn] = fma2(a1, pk2(bv[jn].z, bv[jn].w), acc[jm][jn]);
                        }
                    }
                }
                __syncthreads();
            }
            float* dg = g_dg + z * BE;
#pragma unroll
            for (int jn = 0; jn < 4; jn++) {
                int e = e0 + tx + 16 * jn;
                if (e < NE) {
                    float scl = g_scale[e];
#pragma unroll
                    for (int jm = 0; jm < 4; jm++) {
                        float2 u = upk2(acc[jm][jn]);
                        dg[(b0 + ty + 16 * jm) * NE + e] = (u.x + u.y) * scl;
                    }
                }
            }
        }
        gbar();

        // ---- Phase N: neuron/synapse/trace dynamics ----
        for (int b = bid; b < BB; b += NBLK) {
            float s_i0, gie0, mem0, s_i1 = 0.f, gie1 = 0.f, mem1 = 0.f;
            int e1 = tid + 256;
            int idx0 = b * NE + tid;
            int idx1 = b * NE + e1;
            neuron_update(idx0, Wei[tid * NE + tid], out, (size_t)t * BE, s_i0, gie0, mem0);
            if (e1 < NE)
                neuron_update(idx1, Wei[e1 * NE + e1], out, (size_t)t * BE, s_i1, gie1, mem1);
            // block-sum of spike_i (exact: 0/1 floats)
            float v = s_i0 + s_i1;
            for (int o = 16; o > 0; o >>= 1) v += __shfl_down_sync(0xffffffffu, v, o);
            if ((tid & 31) == 0) smbuf[tid >> 5] = v;
            __syncthreads();
            if (tid == 0) {
                float S = 0.f;
                for (int w = 0; w < 8; w++) S += smbuf[w];
                smbuf[16] = S;
            }
            __syncthreads();
            float S = smbuf[16];
            {
                float dgie = wie * (S - s_i0);
                g_Iie[idx0] = gie0 * (-100.f - mem0);
                g_gie[idx0] = gie0 + (dgie - gie0) * 0.25f;
            }
            if (e1 < NE) {
                float dgie = wie * (S - s_i1);
                g_Iie[idx1] = gie1 * (-100.f - mem1);
                g_gie[idx1] = gie1 + (dgie - gie1) * 0.25f;
            }
            // trace_pre
            const float* xr = xt + (size_t)b * NIN;
            float* trp = g_trp + (size_t)b * NIN;
            for (int i = tid; i < NIN; i += 256) {
                float xv = xr[i];
                float tv;
                if (t == 0) tv = xv;
                else tv = (xv > 0.9f) ? 1.f : trp[i] * (1.0f - 0.5f / 20.0f);
                trp[i] = tv;
            }
            __syncthreads();
        }
        gbar();

        // ---- Phase S: dw_z[e,i] = sum_{b in z} a1[b,e]*x[b,i] + a2[b,e]*trp[b,i] ----
        if (bid < 7 * 13 * SZ) {
            int z = bid / 91, r = bid % 91;
            int ix = r % 13, ey = r / 13;
            int i0 = ix * 64, e0 = ey * 64;
            int bz = z * 176;
            int nkt = (z == SZ - 1) ? 10 : 11;          // chunks of BK=16
            float* A1s = smbuf;                          // [16][68]
            float* A2s = smbuf + 1088;
            float* Xs  = smbuf + 2176;
            float* Ts  = smbuf + 3264;
            int tx = tid & 15, ty = tid >> 4;
            int lrow = tid >> 4;            // 0..15 (k row)
            int lcol = (tid & 15) * 4;      // 0..60 (column chunk)
            bool e_ok = (e0 + lcol + 3) < NE;
            bool i_ok = (i0 + lcol + 3) < NIN;
            u64 acc[4][2];
#pragma unroll
            for (int jm = 0; jm < 4; jm++) { acc[jm][0] = 0ULL; acc[jm][1] = 0ULL; }

            for (int kt = 0; kt < nkt; kt++) {
                int kb = bz + kt * 16 + lrow;
                *(float4*)&A1s[lrow * 68 + lcol] = e_ok ? *(const float4*)&g_a1[kb * NE + e0 + lcol] : f4z;
                *(float4*)&A2s[lrow * 68 + lcol] = e_ok ? *(const float4*)&g_a2[kb * NE + e0 + lcol] : f4z;
                *(float4*)&Xs[lrow * 68 + lcol]  = i_ok ? *(const float4*)&xt[kb * NIN + i0 + lcol] : f4z;
                *(float4*)&Ts[lrow * 68 + lcol]  = i_ok ? *(const float4*)&g_trp[kb * NIN + i0 + lcol] : f4z;
                __syncthreads();
#pragma unroll
                for (int k = 0; k < 16; k++) {
                    float4 a1v = *(const float4*)&A1s[k * 68 + ty * 4];
                    float4 a2v = *(const float4*)&A2s[k * 68 + ty * 4];
                    float4 xv  = *(const float4*)&Xs[k * 68 + tx * 4];
                    float4 tv  = *(const float4*)&Ts[k * 68 + tx * 4];
                    u64 xp0 = pk2(xv.x, xv.y), xp1 = pk2(xv.z, xv.w);
                    u64 tq0 = pk2(tv.x, tv.y), tq1 = pk2(tv.z, tv.w);
                    float a1a[4] = {a1v.x, a1v.y, a1v.z, a1v.w};
                    float a2a[4] = {a2v.x, a2v.y, a2v.z, a2v.w};
#pragma unroll
                    for (int jm = 0; jm < 4; jm++) {
                        u64 a1b = pk2(a1a[jm], a1a[jm]);
                        u64 a2b = pk2(a2a[jm], a2a[jm]);
                        acc[jm][0] = fma2(a1b, xp0, acc[jm][0]);
                        acc[jm][0] = fma2(a2b, tq0, acc[jm][0]);
                        acc[jm][1] = fma2(a1b, xp1, acc[jm][1]);
                        acc[jm][1] = fma2(a2b, tq1, acc[jm][1]);
                    }
                }
                __syncthreads();
            }
            float* dw = g_dw + z * WSZ;
            int ii = i0 + tx * 4;
            if (ii + 3 < NIN) {
#pragma unroll
                for (int jm = 0; jm < 4; jm++) {
                    int e = e0 + ty * 4 + jm;
                    if (e < NE) {
                        float2 u0 = upk2(acc[jm][0]);
                        float2 u1 = upk2(acc[jm][1]);
                        float4 o = make_float4(u0.x, u0.y, u1.x, u1.y);
                        *(float4*)&dw[e * NIN + ii] = o;
                    }
                }
            }
        }
        gbar();
    }
}

// ---------------- launch ----------------
extern "C" void kernel_launch(void* const* d_in, const int* in_sizes, int n_in,
                              void* d_out, int out_size) {
    const float* x = nullptr; const float* Wine = nullptr;
    const float* Wei = nullptr; const float* Wie = nullptr;
    for (int i = 0; i < n_in; i++) {
        int sz = in_sizes[i];
        if (sz == TS * BI) x = (const float*)d_in[i];
        else if (sz == WSZ) Wine = (const float*)d_in[i];
        else if (sz == NE * NE) { if (!Wei) Wei = (const float*)d_in[i]; else Wie = (const float*)d_in[i]; }
    }
    float* out = (float*)d_out;
    k_persist<<<NBLK, 256>>>(x, Wei, Wie, Wine, out);
}

// round 8
// speedup vs baseline: 2.1045x; 1.0330x over previous
#include <cuda_runtime.h>

#define TS  50
#define BB  512
#define NE  400
#define NIN 784
#define BE  (BB*NE)
#define BI  (BB*NIN)
#define WSZ (NE*NIN)
#define NBLK 296
#define GZ  5     // gemm1 split-K parts (K=784 -> 160,160,160,160,144)
#define SZ  3     // stdp  split-K parts (B=512 -> 176,176,160)

typedef unsigned long long u64;

// ---------------- f32x2 helpers ----------------
__device__ __forceinline__ u64 fma2(u64 a, u64 b, u64 c) {
    u64 d;
    asm("fma.rn.f32x2 %0, %1, %2, %3;" : "=l"(d) : "l"(a), "l"(b), "l"(c));
    return d;
}
__device__ __forceinline__ u64 pk2(float lo, float hi) {
    u64 r; asm("mov.b64 %0, {%1, %2};" : "=l"(r) : "f"(lo), "f"(hi)); return r;
}
__device__ __forceinline__ float2 upk2(u64 v) {
    float2 u; asm("mov.b64 {%0, %1}, %2;" : "=f"(u.x), "=f"(u.y) : "l"(v)); return u;
}

// ---------------- persistent device state ----------------
__device__ float g_W[WSZ];
__device__ float g_dw[SZ * WSZ];
__device__ float g_scale[NE];
__device__ float g_dg[GZ * BE];
__device__ float g_gine[BE], g_gei[BE], g_gie[BE], g_Iie[BE];
__device__ float g_meme[BE], g_rce[BE], g_memi[BE], g_rci[BE];
__device__ float g_theta[BE], g_tp1[BE], g_tp2[BE];
__device__ float g_a1[BE], g_a2[BE];
__device__ float g_trp[BI];

// ---------------- grid barrier (CG-style: fences in thread 0 only) ----------------
__device__ unsigned g_count;
__device__ unsigned g_gen;

__device__ __forceinline__ void gbar() {
    __syncthreads();               // orders all threads' stores before thread0's release
    if (threadIdx.x == 0) {
        __threadfence();           // release: my CTA's writes -> visible (gpu scope)
        unsigned gen = *(volatile unsigned*)&g_gen;
        if (atomicAdd(&g_count, 1u) == NBLK - 1) {
            g_count = 0;
            __threadfence();
            *(volatile unsigned*)&g_gen = gen + 1;
        } else {
            while (*(volatile unsigned*)&g_gen == gen) { __nanosleep(40); }
        }
        __threadfence();           // acquire: CCTL.IVALL drops stale L1 (SM-wide)
    }
    __syncthreads();
}

// ---------------- neuron state update (one e/i pair) ----------------
__device__ __forceinline__ void neuron_update(int idx, float wei_diag,
                                              float* __restrict__ out, size_t out_off,
                                              float& s_i_out, float& gie_old_out, float& meme_out) {
    float dg = 0.f;
#pragma unroll
    for (int z = 0; z < GZ; z++) dg += g_dg[z * BE + idx];
    float gine = g_gine[idx];
    float meme = g_meme[idx];
    float Iie = g_Iie[idx];
    float Iine = gine * (0.f - meme);                 // E_EE = 0
    gine += (dg - gine) * 0.5f;                        // DT/TAU_SYN_E
    g_gine[idx] = gine;
    float theta = g_theta[idx];
    float thr = -52.f - 20.f + theta;
    float rce = g_rce[idx];
    bool act = (rce <= 0.f);
    if (act) meme += (-65.f - meme + (Iine + Iie)) * 0.005f;   // DT/TAU_MEM_E
    rce = fmaxf(rce - 0.5f, 0.f);
    float s = (act && meme > thr) ? 1.f : 0.f;
    if (s > 0.f) { meme = -65.f; rce = 5.f; }
    g_meme[idx] = meme; g_rce[idx] = rce;
    // e -> i (diagonal W_ei)
    float dgei = s * wei_diag;
    float gei = g_gei[idx];
    float memi = g_memi[idx];
    float Iei = gei * (0.f - memi);                   // E_EI = 0
    gei += (dgei - gei) * 0.5f;
    g_gei[idx] = gei;
    float rci = g_rci[idx];
    bool acti = (rci <= 0.f);
    if (acti) memi += (-60.f - memi + Iei) * 0.05f;   // DT/TAU_MEM_I
    rci = fmaxf(rci - 0.5f, 0.f);
    float s_i = (acti && memi > -40.f) ? 1.f : 0.f;
    if (s_i > 0.f) { memi = -45.f; rci = 2.f; }
    g_memi[idx] = memi; g_rci[idx] = rci;
    // homeostasis + traces + STDP operands
    theta = theta * (1.0f - 0.5f / 1e7f) + 0.05f * s;
    g_theta[idx] = theta;
    float tp1 = g_tp1[idx], tp2 = g_tp2[idx];
    float r1 = tp1 * (1.0f - 0.5f / 20.0f);
    float r2 = tp2 * (1.0f - 0.5f / 40.0f);
    bool fired = (s > 0.9f);
    g_tp1[idx] = fired ? 1.f : r1;
    g_tp2[idx] = fired ? 1.f : r2;
    g_a1[idx] = 1e-4f * r1;                           // NU_PRE folded
    g_a2[idx] = fired ? 0.01f * r2 : 0.f;             // NU_POST * spike * ret2
    out[out_off + idx] = s;
    s_i_out = s_i; gie_old_out = g_gie[idx]; meme_out = meme;
}

// ---------------- the single persistent kernel ----------------
__global__ void __launch_bounds__(256, 2) k_persist(const float* __restrict__ x,
                                                    const float* __restrict__ Wei,
                                                    const float* __restrict__ Wie,
                                                    const float* __restrict__ Wine,
                                                    float* __restrict__ out) {
    __shared__ __align__(16) float smbuf[4608];     // 18.4KB: unioned per phase
    const int bid = blockIdx.x, tid = threadIdx.x;
    const int gtid = bid * 256 + tid;
    const int sub = tid >> 7;          // half-block id (0/1)
    const int stid = tid & 127;        // lane within half-block
    const float4 f4z = make_float4(0.f, 0.f, 0.f, 0.f);

    // ---- Phase I: init all state ----
    for (int i = gtid; i < SZ * WSZ; i += NBLK * 256) {
        if (i < WSZ) g_W[i] = Wine[i];
        g_dw[i] = 0.f;
        if (i < BE) {
            g_gine[i] = 0.f; g_gei[i] = 0.f; g_gie[i] = 0.f; g_Iie[i] = 0.f;
            g_meme[i] = -65.f; g_rce[i] = 0.f;
            g_memi[i] = -60.f; g_rci[i] = 0.f;
            g_theta[i] = 20.f; g_tp1[i] = 0.f; g_tp2[i] = 0.f;
        }
        if (i < BI) g_trp[i] = 0.f;
        if (i < NE) g_scale[i] = 1.f;
    }
    gbar();

    const float wie = Wie[1];    // uniform off-diagonal (17.0)

    for (int t = 0; t < TS; t++) {
        const float* xt = x + (size_t)t * BI;

        // ---- Phase W: one row per HALF-block (592 slots >= 400, single round) ----
        {
            int e = bid * 2 + sub;
            bool rowok = e < NE;
            float sum = 0.f;
            if (rowok) {
                float s = g_scale[e];
                int base = e * NIN;
                for (int i = stid; i < NIN; i += 128) {
                    float w = g_W[base + i] * s;
#pragma unroll
                    for (int z = 0; z < SZ; z++) w += g_dw[z * WSZ + base + i];
                    w = fminf(fmaxf(w, 0.f), 1.f);
                    g_W[base + i] = w;
                    sum += w;
                }
            }
            for (int o = 16; o > 0; o >>= 1) sum += __shfl_down_sync(0xffffffffu, sum, o);
            if ((tid & 31) == 0) smbuf[tid >> 5] = sum;   // 8 warp sums
            __syncthreads();
            if (rowok && stid == 0) {
                float tt = smbuf[sub * 4] + smbuf[sub * 4 + 1] + smbuf[sub * 4 + 2] + smbuf[sub * 4 + 3];
                g_scale[e] = 78.4f / tt;
            }
        }
        gbar();

        // ---- Phase G: dg_z[b,e] = scale[e] * sum_{k in z} x[b,k]*W[e,k] ----
        if (bid < 7 * 8 * GZ) {
            int z = bid / 56, r = bid % 56;
            int ex = r % 7, by = r / 7;
            int e0 = ex * 64, b0 = by * 64;
            int kz = z * 160;
            int nk = (z == GZ - 1) ? 9 : 10;            // chunks of BK=16
            float* As = smbuf;                          // [64][20]
            float* Bs = smbuf + 1280;                   // [64][20]
            int tx = tid & 15, ty = tid >> 4;
            int lrow = tid >> 2, lk = (tid & 3) * 4;
            u64 acc[4][4];
#pragma unroll
            for (int jm = 0; jm < 4; jm++)
#pragma unroll
                for (int jn = 0; jn < 4; jn++) acc[jm][jn] = 0ULL;

            for (int c = 0; c < nk; c++) {
                int kg = kz + c * 16 + lk;
                *(float4*)&As[lrow * 20 + lk] = *(const float4*)&xt[(b0 + lrow) * NIN + kg];
                int e = e0 + lrow;
                *(float4*)&Bs[lrow * 20 + lk] = (e < NE) ? *(const float4*)&g_W[e * NIN + kg] : f4z;
                __syncthreads();
#pragma unroll
                for (int kk = 0; kk < 16; kk += 4) {
                    float4 av[4], bv[4];
#pragma unroll
                    for (int jm = 0; jm < 4; jm++) av[jm] = *(const float4*)&As[(ty + 16 * jm) * 20 + kk];
#pragma unroll
                    for (int jn = 0; jn < 4; jn++) bv[jn] = *(const float4*)&Bs[(tx + 16 * jn) * 20 + kk];
#pragma unroll
                    for (int jm = 0; jm < 4; jm++) {
                        u64 a0 = pk2(av[jm].x, av[jm].y);
                        u64 a1 = pk2(av[jm].z, av[jm].w);
#pragma unroll
                        for (int jn = 0; jn < 4; jn++) {
                            acc[jm][jn] = fma2(a0, pk2(bv[jn].x, bv[jn].y), acc[jm][jn]);
                            acc[jm][jn] = fma2(a1, pk2(bv[jn].z, bv[jn].w), acc[jm][jn]);
                        }
                    }
                }
                __syncthreads();
            }
            float* dg = g_dg + z * BE;
#pragma unroll
            for (int jn = 0; jn < 4; jn++) {
                int e = e0 + tx + 16 * jn;
                if (e < NE) {
                    float scl = g_scale[e];
#pragma unroll
                    for (int jm = 0; jm < 4; jm++) {
                        float2 u = upk2(acc[jm][jn]);
                        dg[(b0 + ty + 16 * jm) * NE + e] = (u.x + u.y) * scl;
                    }
                }
            }
        }
        gbar();

        // ---- Phase N: one batch per HALF-block (592 slots >= 512, single round) ----
        {
            int b = bid * 2 + sub;
            bool bok = b < BB;
            float s_i[4], gie_o[4], mem_n[4];
            float ssum = 0.f;
#pragma unroll
            for (int j = 0; j < 4; j++) { s_i[j] = 0.f; gie_o[j] = 0.f; mem_n[j] = 0.f; }
            if (bok) {
#pragma unroll
                for (int j = 0; j < 4; j++) {
                    int e = stid + j * 128;
                    if (e < NE) {
                        neuron_update(b * NE + e, Wei[e * NE + e], out, (size_t)t * BE,
                                      s_i[j], gie_o[j], mem_n[j]);
                        ssum += s_i[j];
                    }
                }
            }
            // per-half-block sum of spike_i (exact: 0/1 floats)
            for (int o = 16; o > 0; o >>= 1) ssum += __shfl_down_sync(0xffffffffu, ssum, o);
            if ((tid & 31) == 0) smbuf[tid >> 5] = ssum;
            __syncthreads();
            if (tid == 0) smbuf[8]  = smbuf[0] + smbuf[1] + smbuf[2] + smbuf[3];
            if (tid == 128) smbuf[9] = smbuf[4] + smbuf[5] + smbuf[6] + smbuf[7];
            __syncthreads();
            float S = smbuf[8 + sub];
            if (bok) {
#pragma unroll
                for (int j = 0; j < 4; j++) {
                    int e = stid + j * 128;
                    if (e < NE) {
                        int idx = b * NE + e;
                        float dgie = wie * (S - s_i[j]);           // (ones-eye)*c, exact
                        g_Iie[idx] = gie_o[j] * (-100.f - mem_n[j]);  // NEW mem_e, OLD g_ie
                        g_gie[idx] = gie_o[j] + (dgie - gie_o[j]) * 0.25f;
                    }
                }
                // trace_pre for this batch row
                const float* xr = xt + (size_t)b * NIN;
                float* trp = g_trp + (size_t)b * NIN;
                if (t == 0) {
                    for (int i = stid; i < NIN; i += 128) trp[i] = xr[i];
                } else {
                    for (int i = stid; i < NIN; i += 128) {
                        float xv = xr[i];
                        trp[i] = (xv > 0.9f) ? 1.f : trp[i] * (1.0f - 0.5f / 20.0f);
                    }
                }
            }
        }
        gbar();

        // ---- Phase S: dw_z[e,i] = sum_{b in z} a1[b,e]*x[b,i] + a2[b,e]*trp[b,i] ----
        if (bid < 7 * 13 * SZ) {
            int z = bid / 91, r = bid % 91;
            int ix = r % 13, ey = r / 13;
            int i0 = ix * 64, e0 = ey * 64;
            int bz = z * 176;
            int nkt = (z == SZ - 1) ? 10 : 11;          // chunks of BK=16
            float* A1s = smbuf;                          // [16][68]
            float* A2s = smbuf + 1088;
            float* Xs  = smbuf + 2176;
            float* Ts  = smbuf + 3264;
            int tx = tid & 15, ty = tid >> 4;
            int lrow = tid >> 4;            // 0..15 (k row)
            int lcol = (tid & 15) * 4;      // 0..60 (column chunk)
            bool e_ok = (e0 + lcol + 3) < NE;
            bool i_ok = (i0 + lcol + 3) < NIN;
            u64 acc[4][2];
#pragma unroll
            for (int jm = 0; jm < 4; jm++) { acc[jm][0] = 0ULL; acc[jm][1] = 0ULL; }

            for (int kt = 0; kt < nkt; kt++) {
                int kb = bz + kt * 16 + lrow;
                *(float4*)&A1s[lrow * 68 + lcol] = e_ok ? *(const float4*)&g_a1[kb * NE + e0 + lcol] : f4z;
                *(float4*)&A2s[lrow * 68 + lcol] = e_ok ? *(const float4*)&g_a2[kb * NE + e0 + lcol] : f4z;
                *(float4*)&Xs[lrow * 68 + lcol]  = i_ok ? *(const float4*)&xt[kb * NIN + i0 + lcol] : f4z;
                *(float4*)&Ts[lrow * 68 + lcol]  = i_ok ? *(const float4*)&g_trp[kb * NIN + i0 + lcol] : f4z;
                __syncthreads();
#pragma unroll
                for (int k = 0; k < 16; k++) {
                    float4 a1v = *(const float4*)&A1s[k * 68 + ty * 4];
                    float4 a2v = *(const float4*)&A2s[k * 68 + ty * 4];
                    float4 xv  = *(const float4*)&Xs[k * 68 + tx * 4];
                    float4 tv  = *(const float4*)&Ts[k * 68 + tx * 4];
                    u64 xp0 = pk2(xv.x, xv.y), xp1 = pk2(xv.z, xv.w);
                    u64 tq0 = pk2(tv.x, tv.y), tq1 = pk2(tv.z, tv.w);
                    float a1a[4] = {a1v.x, a1v.y, a1v.z, a1v.w};
                    float a2a[4] = {a2v.x, a2v.y, a2v.z, a2v.w};
#pragma unroll
                    for (int jm = 0; jm < 4; jm++) {
                        u64 a1b = pk2(a1a[jm], a1a[jm]);
                        u64 a2b = pk2(a2a[jm], a2a[jm]);
                        acc[jm][0] = fma2(a1b, xp0, acc[jm][0]);
                        acc[jm][0] = fma2(a2b, tq0, acc[jm][0]);
                        acc[jm][1] = fma2(a1b, xp1, acc[jm][1]);
                        acc[jm][1] = fma2(a2b, tq1, acc[jm][1]);
                    }
                }
                __syncthreads();
            }
            float* dw = g_dw + z * WSZ;
            int ii = i0 + tx * 4;
            if (ii + 3 < NIN) {
#pragma unroll
                for (int jm = 0; jm < 4; jm++) {
                    int e = e0 + ty * 4 + jm;
                    if (e < NE) {
                        float2 u0 = upk2(acc[jm][0]);
                        float2 u1 = upk2(acc[jm][1]);
                        float4 o = make_float4(u0.x, u0.y, u1.x, u1.y);
                        *(float4*)&dw[e * NIN + ii] = o;
                    }
                }
            }
        }
        gbar();
    }
}

// ---------------- launch ----------------
extern "C" void kernel_launch(void* const* d_in, const int* in_sizes, int n_in,
                              void* d_out, int out_size) {
    const float* x = nullptr; const float* Wine = nullptr;
    const float* Wei = nullptr; const float* Wie = nullptr;
    for (int i = 0; i < n_in; i++) {
        int sz = in_sizes[i];
        if (sz == TS * BI) x = (const float*)d_in[i];
        else if (sz == WSZ) Wine = (const float*)d_in[i];
        else if (sz == NE * NE) { if (!Wei) Wei = (const float*)d_in[i]; else Wie = (const float*)d_in[i]; }
    }
    float* out = (float*)d_out;
    k_persist<<<NBLK, 256>>>(x, Wei, Wie, Wine, out);
}

// round 9
// speedup vs baseline: 2.2620x; 1.0748x over previous
#include <cuda_runtime.h>

#define TS  50
#define BB  512
#define NE  400
#define NIN 784
#define BE  (BB*NE)
#define BI  (BB*NIN)
#define WSZ (NE*NIN)
#define NBLK 296
#define GZ  5     // gemm1 split-K parts (K=784 -> 160x4,144)
#define SZ  3     // stdp  split-K parts (B=512 -> 176,176,160)

#define WS_STRIDE 164
#define SM_AS     10496            // after Ws (64*164)
#define SMEM_FLOATS (SM_AS + 2*64*20)   // 13056
#define SMEM_BYTES  (SMEM_FLOATS*4 + 256)

typedef unsigned long long u64;

// ---------------- f32x2 helpers ----------------
__device__ __forceinline__ u64 fma2(u64 a, u64 b, u64 c) {
    u64 d;
    asm("fma.rn.f32x2 %0, %1, %2, %3;" : "=l"(d) : "l"(a), "l"(b), "l"(c));
    return d;
}
__device__ __forceinline__ u64 pk2(float lo, float hi) {
    u64 r; asm("mov.b64 %0, {%1, %2};" : "=l"(r) : "f"(lo), "f"(hi)); return r;
}
__device__ __forceinline__ float2 upk2(u64 v) {
    float2 u; asm("mov.b64 {%0, %1}, %2;" : "=f"(u.x), "=f"(u.y) : "l"(v)); return u;
}

// ---------------- persistent device state ----------------
__device__ float g_Wbuf[2 * WSZ];          // double-buffered pre-normalized W
__device__ float g_rs[2 * GZ * NE];        // double-buffered row-sum partials per z
__device__ float g_dw[SZ * WSZ];
__device__ float g_dg[GZ * BE];            // UNSCALED dg partials
__device__ float g_gine[BE], g_gei[BE], g_gie[BE], g_Iie[BE];
__device__ float g_meme[BE], g_rce[BE], g_memi[BE], g_rci[BE];
__device__ float g_theta[BE], g_tp1[BE], g_tp2[BE];
__device__ float g_a1[BE], g_a2[BE];
__device__ float g_trp[BI];

// ---------------- grid barrier (CG-style) ----------------
__device__ unsigned g_count;
__device__ unsigned g_gen;

__device__ __forceinline__ void gbar() {
    __syncthreads();
    if (threadIdx.x == 0) {
        __threadfence();
        unsigned gen = *(volatile unsigned*)&g_gen;
        if (atomicAdd(&g_count, 1u) == NBLK - 1) {
            g_count = 0;
            __threadfence();
            *(volatile unsigned*)&g_gen = gen + 1;
        } else {
            while (*(volatile unsigned*)&g_gen == gen) { __nanosleep(40); }
        }
        __threadfence();
    }
    __syncthreads();
}

// ---------------- neuron state update (one e/i pair) ----------------
__device__ __forceinline__ void neuron_update(int idx, float scl, float wei_diag,
                                              float* __restrict__ out, size_t out_off,
                                              float& s_i_out, float& gie_old_out, float& meme_out) {
    float dg = __fmul_rn(g_dg[idx], scl);
#pragma unroll
    for (int z = 1; z < GZ; z++) dg = __fadd_rn(dg, __fmul_rn(g_dg[z * BE + idx], scl));
    float gine = g_gine[idx];
    float meme = g_meme[idx];
    float Iie = g_Iie[idx];
    float Iine = gine * (0.f - meme);                 // E_EE = 0
    gine += (dg - gine) * 0.5f;                        // DT/TAU_SYN_E
    g_gine[idx] = gine;
    float theta = g_theta[idx];
    float thr = -52.f - 20.f + theta;
    float rce = g_rce[idx];
    bool act = (rce <= 0.f);
    if (act) meme += (-65.f - meme + (Iine + Iie)) * 0.005f;   // DT/TAU_MEM_E
    rce = fmaxf(rce - 0.5f, 0.f);
    float s = (act && meme > thr) ? 1.f : 0.f;
    if (s > 0.f) { meme = -65.f; rce = 5.f; }
    g_meme[idx] = meme; g_rce[idx] = rce;
    // e -> i (diagonal W_ei)
    float dgei = s * wei_diag;
    float gei = g_gei[idx];
    float memi = g_memi[idx];
    float Iei = gei * (0.f - memi);                   // E_EI = 0
    gei += (dgei - gei) * 0.5f;
    g_gei[idx] = gei;
    float rci = g_rci[idx];
    bool acti = (rci <= 0.f);
    if (acti) memi += (-60.f - memi + Iei) * 0.05f;   // DT/TAU_MEM_I
    rci = fmaxf(rci - 0.5f, 0.f);
    float s_i = (acti && memi > -40.f) ? 1.f : 0.f;
    if (s_i > 0.f) { memi = -45.f; rci = 2.f; }
    g_memi[idx] = memi; g_rci[idx] = rci;
    // homeostasis + traces + STDP operands
    theta = theta * (1.0f - 0.5f / 1e7f) + 0.05f * s;
    g_theta[idx] = theta;
    float tp1 = g_tp1[idx], tp2 = g_tp2[idx];
    float r1 = tp1 * (1.0f - 0.5f / 20.0f);
    float r2 = tp2 * (1.0f - 0.5f / 40.0f);
    bool fired = (s > 0.9f);
    g_tp1[idx] = fired ? 1.f : r1;
    g_tp2[idx] = fired ? 1.f : r2;
    g_a1[idx] = 1e-4f * r1;                           // NU_PRE folded
    g_a2[idx] = fired ? 0.01f * r2 : 0.f;             // NU_POST * spike * ret2
    out[out_off + idx] = s;
    s_i_out = s_i; gie_old_out = g_gie[idx]; meme_out = meme;
}

// ---------------- the single persistent kernel ----------------
__global__ void __launch_bounds__(256, 2) k_persist(const float* __restrict__ x,
                                                    const float* __restrict__ Wei,
                                                    const float* __restrict__ Wie,
                                                    const float* __restrict__ Wine,
                                                    float* __restrict__ out) {
    extern __shared__ __align__(16) float smem[];
    const int bid = blockIdx.x, tid = threadIdx.x;
    const int gtid = bid * 256 + tid;
    const int sub = tid >> 7;          // half-block id (0/1)
    const int stid = tid & 127;        // lane within half-block
    const float4 f4z = make_float4(0.f, 0.f, 0.f, 0.f);

    // ---- Phase I: init all state ----
    for (int i = gtid; i < SZ * WSZ; i += NBLK * 256) {
        if (i < WSZ) g_Wbuf[i] = Wine[i];       // buffer 0
        g_dw[i] = 0.f;
        if (i < BE) {
            g_gine[i] = 0.f; g_gei[i] = 0.f; g_gie[i] = 0.f; g_Iie[i] = 0.f;
            g_meme[i] = -65.f; g_rce[i] = 0.f;
            g_memi[i] = -60.f; g_rci[i] = 0.f;
            g_theta[i] = 20.f; g_tp1[i] = 0.f; g_tp2[i] = 0.f;
        }
        if (i < BI) g_trp[i] = 0.f;
        if (i < GZ * NE) g_rs[i] = (i < NE) ? 78.4f : 0.f;   // buffer 0: s_{-1} = 1
    }
    gbar();

    const float wie = Wie[1];    // uniform off-diagonal (17.0)

    for (int t = 0; t < TS; t++) {
        const float* xt = x + (size_t)t * BI;
        const int p = t & 1;

        // ---- Phase G': W-update (fused) + GEMM dg_z = x @ w_new.T (unscaled) ----
        if (bid < 7 * 8 * GZ) {
            int z = bid / 56, r = bid % 56;
            int ex = r % 7, by = r / 7;
            int e0 = ex * 64, b0 = by * 64;
            int kz = z * 160;
            int nk = (z == GZ - 1) ? 9 : 10;            // chunks of BK=16
            float* Ws = smem;                           // [64][WS_STRIDE]
            float* As = smem + SM_AS;                   // [2][64][20]
            int lrow = tid >> 2, lk4 = (tid & 3) * 4;
            int e = e0 + lrow;
            bool eok = e < NE;

            // prefetch first x chunk early
            float4 xreg = *(const float4*)&xt[(b0 + lrow) * NIN + kz + lk4];

            // scale_prev from previous step's row-sum partials
            float sprev = 0.f;
            if (eok) {
                const float* rsp = g_rs + p * GZ * NE;
                float rsum = rsp[e];
#pragma unroll
                for (int zz = 1; zz < GZ; zz++) rsum += rsp[zz * NE + e];
                sprev = 78.4f / rsum;
            }
            // bulk W update into smem (and persist from b-tile 0)
            const float* Wold = g_Wbuf + p * WSZ;
            float* Wnew = g_Wbuf + (p ^ 1) * WSZ;
            float rsacc = 0.f;
#pragma unroll 5
            for (int c = 0; c < nk; c++) {
                int kg = kz + c * 16 + lk4;
                float4 w4 = f4z, d0 = f4z, d1 = f4z, d2 = f4z;
                if (eok) {
                    int gi = e * NIN + kg;
                    w4 = *(const float4*)&Wold[gi];
                    d0 = *(const float4*)&g_dw[gi];
                    d1 = *(const float4*)&g_dw[WSZ + gi];
                    d2 = *(const float4*)&g_dw[2 * WSZ + gi];
                }
                float4 wn;
                wn.x = fminf(fmaxf(w4.x * sprev + d0.x + d1.x + d2.x, 0.f), 1.f);
                wn.y = fminf(fmaxf(w4.y * sprev + d0.y + d1.y + d2.y, 0.f), 1.f);
                wn.z = fminf(fmaxf(w4.z * sprev + d0.z + d1.z + d2.z, 0.f), 1.f);
                wn.w = fminf(fmaxf(w4.w * sprev + d0.w + d1.w + d2.w, 0.f), 1.f);
                *(float4*)&Ws[lrow * WS_STRIDE + c * 16 + lk4] = wn;
                if (by == 0 && eok) *(float4*)&Wnew[e * NIN + kg] = wn;
                rsacc += wn.x + wn.y + wn.z + wn.w;
            }
            rsacc += __shfl_xor_sync(0xffffffffu, rsacc, 1);
            rsacc += __shfl_xor_sync(0xffffffffu, rsacc, 2);
            if (by == 0 && eok && (tid & 3) == 0)
                g_rs[(p ^ 1) * GZ * NE + z * NE + e] = rsacc;
            __syncthreads();

            // GEMM: stream x chunks with double-buffered smem + reg prefetch
            int tx = tid & 15, ty = tid >> 4;
            u64 acc[4][4];
#pragma unroll
            for (int jm = 0; jm < 4; jm++)
#pragma unroll
                for (int jn = 0; jn < 4; jn++) acc[jm][jn] = 0ULL;

            for (int c = 0; c < nk; c++) {
                float* Ab = As + (c & 1) * 1280;
                *(float4*)&Ab[lrow * 20 + lk4] = xreg;
                __syncthreads();
                if (c + 1 < nk)
                    xreg = *(const float4*)&xt[(b0 + lrow) * NIN + kz + (c + 1) * 16 + lk4];
#pragma unroll
                for (int kk = 0; kk < 16; kk += 4) {
                    float4 av[4], bv[4];
#pragma unroll
                    for (int jm = 0; jm < 4; jm++) av[jm] = *(const float4*)&Ab[(ty + 16 * jm) * 20 + kk];
#pragma unroll
                    for (int jn = 0; jn < 4; jn++) bv[jn] = *(const float4*)&Ws[(tx + 16 * jn) * WS_STRIDE + c * 16 + kk];
#pragma unroll
                    for (int jm = 0; jm < 4; jm++) {
                        u64 a0 = pk2(av[jm].x, av[jm].y);
                        u64 a1 = pk2(av[jm].z, av[jm].w);
#pragma unroll
                        for (int jn = 0; jn < 4; jn++) {
                            acc[jm][jn] = fma2(a0, pk2(bv[jn].x, bv[jn].y), acc[jm][jn]);
                            acc[jm][jn] = fma2(a1, pk2(bv[jn].z, bv[jn].w), acc[jm][jn]);
                        }
                    }
                }
            }
            float* dg = g_dg + z * BE;
#pragma unroll
            for (int jn = 0; jn < 4; jn++) {
                int ee = e0 + tx + 16 * jn;
                if (ee < NE) {
#pragma unroll
                    for (int jm = 0; jm < 4; jm++) {
                        float2 u = upk2(acc[jm][jn]);
                        dg[(b0 + ty + 16 * jm) * NE + ee] = u.x + u.y;
                    }
                }
            }
        }
        gbar();

        // ---- Phase N: scale + neuron/synapse/trace dynamics (one batch per half-block) ----
        {
            const float* rsn = g_rs + (p ^ 1) * GZ * NE;
            int b = bid * 2 + sub;
            bool bok = b < BB;
            float s_i[4], gie_o[4], mem_n[4];
            float ssum = 0.f;
#pragma unroll
            for (int j = 0; j < 4; j++) { s_i[j] = 0.f; gie_o[j] = 0.f; mem_n[j] = 0.f; }
            if (bok) {
#pragma unroll
                for (int j = 0; j < 4; j++) {
                    int e = stid + j * 128;
                    if (e < NE) {
                        float rsum = rsn[e];
#pragma unroll
                        for (int zz = 1; zz < GZ; zz++) rsum += rsn[zz * NE + e];
                        float scl = 78.4f / rsum;
                        neuron_update(b * NE + e, scl, Wei[e * NE + e], out, (size_t)t * BE,
                                      s_i[j], gie_o[j], mem_n[j]);
                        ssum += s_i[j];
                    }
                }
            }
            for (int o = 16; o > 0; o >>= 1) ssum += __shfl_down_sync(0xffffffffu, ssum, o);
            if ((tid & 31) == 0) smem[tid >> 5] = ssum;
            __syncthreads();
            if (tid == 0)   smem[8] = smem[0] + smem[1] + smem[2] + smem[3];
            if (tid == 128) smem[9] = smem[4] + smem[5] + smem[6] + smem[7];
            __syncthreads();
            float S = smem[8 + sub];
            if (bok) {
#pragma unroll
                for (int j = 0; j < 4; j++) {
                    int e = stid + j * 128;
                    if (e < NE) {
                        int idx = b * NE + e;
                        float dgie = wie * (S - s_i[j]);
                        g_Iie[idx] = gie_o[j] * (-100.f - mem_n[j]);
                        g_gie[idx] = gie_o[j] + (dgie - gie_o[j]) * 0.25f;
                    }
                }
                const float* xr = xt + (size_t)b * NIN;
                float* trp = g_trp + (size_t)b * NIN;
                if (t == 0) {
                    for (int i = stid; i < NIN; i += 128) trp[i] = xr[i];
                } else {
                    for (int i = stid; i < NIN; i += 128) {
                        float xv = xr[i];
                        trp[i] = (xv > 0.9f) ? 1.f : trp[i] * (1.0f - 0.5f / 20.0f);
                    }
                }
            }
        }
        gbar();

        // ---- Phase S: dw_z[e,i] = sum_{b in z} a1[b,e]*x[b,i] + a2[b,e]*trp[b,i] ----
        if (bid < 7 * 13 * SZ) {
            int z = bid / 91, r = bid % 91;
            int ix = r % 13, ey = r / 13;
            int i0 = ix * 64, e0 = ey * 64;
            int bz = z * 176;
            int nkt = (z == SZ - 1) ? 10 : 11;          // chunks of BK=16
            float* A1s = smem;                           // [16][68]
            float* A2s = smem + 1088;
            float* Xs  = smem + 2176;
            float* Ts  = smem + 3264;
            int tx = tid & 15, ty = tid >> 4;
            int lrow = tid >> 4;            // 0..15 (k row)
            int lcol = (tid & 15) * 4;      // 0..60 (column chunk)
            bool e_ok = (e0 + lcol + 3) < NE;
            bool i_ok = (i0 + lcol + 3) < NIN;
            u64 acc[4][2];
#pragma unroll
            for (int jm = 0; jm < 4; jm++) { acc[jm][0] = 0ULL; acc[jm][1] = 0ULL; }

            // prefetch chunk 0
            int kb0 = bz + lrow;
            float4 pa1 = e_ok ? *(const float4*)&g_a1[kb0 * NE + e0 + lcol] : f4z;
            float4 pa2 = e_ok ? *(const float4*)&g_a2[kb0 * NE + e0 + lcol] : f4z;
            float4 pxv = i_ok ? *(const float4*)&xt[kb0 * NIN + i0 + lcol] : f4z;
            float4 ptv = i_ok ? *(const float4*)&g_trp[kb0 * NIN + i0 + lcol] : f4z;

            for (int kt = 0; kt < nkt; kt++) {
                *(float4*)&A1s[lrow * 68 + lcol] = pa1;
                *(float4*)&A2s[lrow * 68 + lcol] = pa2;
                *(float4*)&Xs[lrow * 68 + lcol]  = pxv;
                *(float4*)&Ts[lrow * 68 + lcol]  = ptv;
                __syncthreads();
                if (kt + 1 < nkt) {
                    int kb = bz + (kt + 1) * 16 + lrow;
                    pa1 = e_ok ? *(const float4*)&g_a1[kb * NE + e0 + lcol] : f4z;
                    pa2 = e_ok ? *(const float4*)&g_a2[kb * NE + e0 + lcol] : f4z;
                    pxv = i_ok ? *(const float4*)&xt[kb * NIN + i0 + lcol] : f4z;
                    ptv = i_ok ? *(const float4*)&g_trp[kb * NIN + i0 + lcol] : f4z;
                }
#pragma unroll
                for (int k = 0; k < 16; k++) {
                    float4 a1v = *(const float4*)&A1s[k * 68 + ty * 4];
                    float4 a2v = *(const float4*)&A2s[k * 68 + ty * 4];
                    float4 xv  = *(const float4*)&Xs[k * 68 + tx * 4];
                    float4 tv  = *(const float4*)&Ts[k * 68 + tx * 4];
                    u64 xp0 = pk2(xv.x, xv.y), xp1 = pk2(xv.z, xv.w);
                    u64 tq0 = pk2(tv.x, tv.y), tq1 = pk2(tv.z, tv.w);
                    float a1a[4] = {a1v.x, a1v.y, a1v.z, a1v.w};
                    float a2a[4] = {a2v.x, a2v.y, a2v.z, a2v.w};
#pragma unroll
                    for (int jm = 0; jm < 4; jm++) {
                        u64 a1b = pk2(a1a[jm], a1a[jm]);
                        u64 a2b = pk2(a2a[jm], a2a[jm]);
                        acc[jm][0] = fma2(a1b, xp0, acc[jm][0]);
                        acc[jm][0] = fma2(a2b, tq0, acc[jm][0]);
                        acc[jm][1] = fma2(a1b, xp1, acc[jm][1]);
                        acc[jm][1] = fma2(a2b, tq1, acc[jm][1]);
                    }
                }
                __syncthreads();
            }
            float* dw = g_dw + z * WSZ;
            int ii = i0 + tx * 4;
            if (ii + 3 < NIN) {
#pragma unroll
                for (int jm = 0; jm < 4; jm++) {
                    int e = e0 + ty * 4 + jm;
                    if (e < NE) {
                        float2 u0 = upk2(acc[jm][0]);
                        float2 u1 = upk2(acc[jm][1]);
                        float4 o = make_float4(u0.x, u0.y, u1.x, u1.y);
                        *(float4*)&dw[e * NIN + ii] = o;
                    }
                }
            }
        }
        gbar();
    }
}

// ---------------- launch ----------------
extern "C" void kernel_launch(void* const* d_in, const int* in_sizes, int n_in,
                              void* d_out, int out_size) {
    const float* x = nullptr; const float* Wine = nullptr;
    const float* Wei = nullptr; const float* Wie = nullptr;
    for (int i = 0; i < n_in; i++) {
        int sz = in_sizes[i];
        if (sz == TS * BI) x = (const float*)d_in[i];
        else if (sz == WSZ) Wine = (const float*)d_in[i];
        else if (sz == NE * NE) { if (!Wei) Wei = (const float*)d_in[i]; else Wie = (const float*)d_in[i]; }
    }
    float* out = (float*)d_out;
    cudaFuncSetAttribute(k_persist, cudaFuncAttributeMaxDynamicSharedMemorySize, SMEM_BYTES);
    k_persist<<<NBLK, 256, SMEM_BYTES>>>(x, Wei, Wie, Wine, out);
}